// round 13
// baseline (speedup 1.0000x reference)
#include <cuda_runtime.h>
#include <math.h>

#define NL 50000
#define KN 16
#define TB 16
#define NB (NL/TB)

typedef unsigned long long u64;

// ---------------- persistent device scratch ----------------
__device__ float g_Wm2[64*64*4];
__device__ float g_Wq2[114*64*4];
__device__ float g_Wo2[128*64*4];
__device__ float g_We2[32*512*4];    // jp padded to 512, pad=0
__device__ float g_Wv2[242*64*4];
__device__ float2 g_bk2[64];
__device__ float g_bv[128];
__device__ float g_df  [(size_t)NL*128];
__device__ float g_c   [NL*2];
__device__ float g_rext[(size_t)NL*968];
__device__ float g_zbar[(size_t)NL*968];

__device__ __forceinline__ void fma2(u64 &d, u64 a, u64 b){
    asm("fma.rn.f32x2 %0, %1, %2, %0;" : "+l"(d) : "l"(a), "l"(b));
}
__device__ __forceinline__ float2 upk(u64 v){
    float lo, hi;
    asm("mov.b64 {%0,%1}, %2;" : "=f"(lo), "=f"(hi) : "l"(v));
    return make_float2(lo, hi);
}
__device__ __forceinline__ float dot4(float4 a, float4 b){
    return fmaf(a.x,b.x, fmaf(a.y,b.y, fmaf(a.z,b.z, a.w*b.w)));
}

// ---- K0: build packed weights ----
__global__ void k0_prep(const float* __restrict__ W_mem, const float* __restrict__ b_mem,
                        const float* __restrict__ W_q,   const float* __restrict__ W_kv,
                        const float* __restrict__ b_kv,  const float* __restrict__ W_out)
{
    const int t = blockIdx.x*blockDim.x + threadIdx.x, nt = gridDim.x*blockDim.x;
    for (int e=t; e<64*64*4; e+=nt){
        int s=e&3, po=(e>>2)&63, j2=e>>8;
        g_Wm2[e] = W_mem[(po + 64*(s&1))*128 + 2*j2 + (s>>1)];
    }
    for (int e=t; e<114*64*4; e+=nt){
        int s=e&3, po=(e>>2)&63, j2=e>>8;
        g_Wq2[e] = W_q[(po + 64*(s&1))*228 + 2*j2 + (s>>1)];
    }
    for (int e=t; e<128*64*4; e+=nt){
        int s=e&3, po=(e>>2)&63, j2=e>>8;
        g_Wo2[e] = W_out[(po + 64*(s&1))*256 + 2*j2 + (s>>1)];
    }
    for (int e=t; e<32*512*4; e+=nt){
        int s=e&3, r=e>>2, jp=r&511, d2=r>>9;
        int d = 2*d2 + (s>>1), h = s&1, i = h*64 + d;
        float v = 0.f;
        if (jp < 484){
            if (jp < 356) v = W_kv[i*356 + jp];
            else { int m=jp-356; float acc=0.f;
                   for (int l=0;l<128;l++) acc = fmaf(W_kv[i*356+l], W_mem[l*128+m], acc);
                   v = acc; }
        }
        g_We2[e] = v;
    }
    for (int e=t; e<242*64*4; e+=nt){
        int s=e&3, r=e>>2, d=r&63, jp2=r>>6;
        int jp = 2*jp2 + (s>>1), h = s&1, i = 128 + h*64 + d;
        float v;
        if (jp < 356) v = W_kv[i*356 + jp];
        else { int m=jp-356; float acc=0.f;
               for (int l=0;l<128;l++) acc = fmaf(W_kv[i*356+l], W_mem[l*128+m], acc);
               v = acc; }
        g_Wv2[e] = v;
    }
    for (int e=t; e<256; e+=nt){
        float s = b_kv[e];
        for (int l=0;l<128;l++) s = fmaf(W_kv[e*356+l], b_mem[l], s);
        if (e < 128){
            if (e < 64) g_bk2[e].x = s; else g_bk2[e-64].y = s;
        } else g_bv[e-128] = s;
    }
}

// ---- K1: df, t_dst, Q, c, rext ----
__global__ void __launch_bounds__(128) k1_qdf(
    const float* __restrict__ memory, const float* __restrict__ dst_feat,
    const float* __restrict__ dst_ts, const int* __restrict__ dst_nodes,
    const float* __restrict__ b_mem,  const float* __restrict__ time_w,
    const float* __restrict__ time_b, const float* __restrict__ b_q)
{
    __shared__ float2 sXd[TB][228];
    __shared__ float2 sMQ[TB][128];
    __shared__ int   sIdx[TB];
    __shared__ float sTs[TB];
    const int tid = threadIdx.x, row0 = blockIdx.x*TB;

    if (tid < TB){ sIdx[tid]=dst_nodes[row0+tid]; sTs[tid]=dst_ts[row0+tid]; }
    __syncthreads();
    for (int e=tid; e<TB*128; e+=128){
        int r=e>>7, c=e&127;
        float v = __ldg(&memory[(size_t)sIdx[r]*128 + c]);
        sMQ[r][c] = make_float2(v, v);
    }
    for (int e=tid; e<TB*100; e+=128){
        int r=e/100, d=e-r*100;
        float v = __cosf(fmaf(sTs[r], time_w[d], time_b[d]));
        sXd[r][128+d] = make_float2(v, v);
    }
    __syncthreads();

    const int po = tid & 63, rg = tid >> 6;
    { // df
        u64 acc[8];
        #pragma unroll
        for (int r=0;r<8;r++) acc[r]=0ull;
        for (int j2=0;j2<64;j2++){
            ulonglong2 w = *(const ulonglong2*)&g_Wm2[(j2*64+po)*4];
            #pragma unroll
            for (int r=0;r<8;r++){
                ulonglong2 x = *(const ulonglong2*)&sMQ[rg*8+r][2*j2];
                fma2(acc[r], w.x, x.x);
                fma2(acc[r], w.y, x.y);
            }
        }
        float bl = b_mem[po], bh = b_mem[po+64];
        #pragma unroll
        for (int r=0;r<8;r++){
            int row = rg*8+r;
            float2 a = upk(acc[r]);
            float lo = a.x + bl + dst_feat[(size_t)(row0+row)*128 + po];
            float hi = a.y + bh + dst_feat[(size_t)(row0+row)*128 + po + 64];
            sXd[row][po]    = make_float2(lo, lo);
            sXd[row][po+64] = make_float2(hi, hi);
            g_df[(size_t)(row0+row)*128 + po]      = lo;
            g_df[(size_t)(row0+row)*128 + po + 64] = hi;
        }
    }
    __syncthreads();
    { // Q
        u64 acc[8];
        #pragma unroll
        for (int r=0;r<8;r++) acc[r]=0ull;
        for (int j2=0;j2<114;j2++){
            ulonglong2 w = *(const ulonglong2*)&g_Wq2[(j2*64+po)*4];
            #pragma unroll
            for (int r=0;r<8;r++){
                ulonglong2 x = *(const ulonglong2*)&sXd[rg*8+r][2*j2];
                fma2(acc[r], w.x, x.x);
                fma2(acc[r], w.y, x.y);
            }
        }
        float bl = b_q[po], bh = b_q[po+64];
        #pragma unroll
        for (int r=0;r<8;r++){
            float2 a = upk(acc[r]);
            sMQ[rg*8+r][po] = make_float2(a.x + bl, a.y + bh);
        }
    }
    __syncthreads();
    if (tid < TB){
        float c0=0.f, c1=0.f;
        for (int d=0;d<64;d++){
            float2 q = sMQ[tid][d], b = g_bk2[d];
            c0 = fmaf(q.x, b.x, c0); c1 = fmaf(q.y, b.y, c1);
        }
        g_c[(row0+tid)*2+0]=c0; g_c[(row0+tid)*2+1]=c1;
    }
    #pragma unroll
    for (int half=0; half<2; half++){
        #pragma unroll
        for (int it=0; it<2; it++){
            const int jpA = tid + it*128;
            const int jpB = jpA + 256;
            u64 aA[8], aB[8];
            #pragma unroll
            for (int r=0;r<8;r++){ aA[r]=0ull; aB[r]=0ull; }
            for (int d2=0;d2<32;d2++){
                ulonglong2 wA = *(const ulonglong2*)&g_We2[(d2*512+jpA)*4];
                ulonglong2 wB = *(const ulonglong2*)&g_We2[(d2*512+jpB)*4];
                #pragma unroll
                for (int r=0;r<8;r++){
                    ulonglong2 x = *(const ulonglong2*)&sMQ[half*8+r][2*d2];
                    fma2(aA[r], wA.x, x.x); fma2(aA[r], wA.y, x.y);
                    fma2(aB[r], wB.x, x.x); fma2(aB[r], wB.y, x.y);
                }
            }
            #pragma unroll
            for (int r=0;r<8;r++){
                int row = row0 + half*8 + r;
                *(float2*)&g_rext[(size_t)row*968 + jpA*2] = upk(aA[r]);
                if (jpB < 484)
                    *(float2*)&g_rext[(size_t)row*968 + jpB*2] = upk(aB[r]);
            }
        }
    }
}

// ---- K2: register-resident features; logits + softmax + partial-zbar ----
__global__ void __launch_bounds__(128) k2_attn(
    const float* __restrict__ memory,  const float* __restrict__ src_feat,
    const float* __restrict__ edge_feat, const float* __restrict__ dst_ts,
    const float* __restrict__ src_ts,  const int* __restrict__ src_nodes,
    const float* __restrict__ time_w,  const float* __restrict__ time_b)
{
    __shared__ float sR[968];
    __shared__ float sP[4][968];
    __shared__ float sLogit[2][KN];
    __shared__ float sAttn[2][KN];
    const int n=blockIdx.x, tid=threadIdx.x, lane=tid&31, w=tid>>5;

    for (int e=tid; e<968; e+=128){
        float v = g_rext[(size_t)n*968 + e];
        sR[(e&1)*484 + (e>>1)] = v;
    }

    float4 sv[4], ev[4], mv[4], tv[4];
    const float dts = dst_ts[n];
    #pragma unroll
    for (int kk=0; kk<4; kk++){
        const int k = w*4 + kk;
        const size_t eb = ((size_t)n*KN + k)*128;
        const int idx = src_nodes[n*KN + k];
        sv[kk] = *(const float4*)&src_feat [eb + lane*4];
        ev[kk] = *(const float4*)&edge_feat[eb + lane*4];
        mv[kk] = __ldg((const float4*)&memory[(size_t)idx*128 + lane*4]);
        float dt = dts - src_ts[n*KN + k]; dt = dt > 0.f ? dt : 0.f;
        tv[kk].x = __cosf(fmaf(dt, time_w[lane   ], time_b[lane   ]));
        tv[kk].y = __cosf(fmaf(dt, time_w[lane+32], time_b[lane+32]));
        tv[kk].z = __cosf(fmaf(dt, time_w[lane+64], time_b[lane+64]));
        tv[kk].w = (lane<4) ? __cosf(fmaf(dt, time_w[lane+96], time_b[lane+96])) : 0.f;
    }
    __syncthreads();

    {
        float a0[4], a1[4];
        #pragma unroll
        for (int kk=0;kk<4;kk++){ a0[kk]=0.f; a1[kk]=0.f; }
        float4 r0, r1;
        r0 = *(const float4*)&sR[lane*4];       r1 = *(const float4*)&sR[484+lane*4];
        #pragma unroll
        for (int kk=0;kk<4;kk++){ a0[kk]+=dot4(r0,sv[kk]); a1[kk]+=dot4(r1,sv[kk]); }
        r0 = *(const float4*)&sR[128+lane*4];   r1 = *(const float4*)&sR[484+128+lane*4];
        #pragma unroll
        for (int kk=0;kk<4;kk++){ a0[kk]+=dot4(r0,ev[kk]); a1[kk]+=dot4(r1,ev[kk]); }
        r0 = *(const float4*)&sR[356+lane*4];   r1 = *(const float4*)&sR[484+356+lane*4];
        #pragma unroll
        for (int kk=0;kk<4;kk++){ a0[kk]+=dot4(r0,mv[kk]); a1[kk]+=dot4(r1,mv[kk]); }
        float t0a = sR[256+lane], t0b = sR[484+256+lane];
        float t1a = sR[288+lane], t1b = sR[484+288+lane];
        float t2a = sR[320+lane], t2b = sR[484+320+lane];
        float t3a = (lane<4)?sR[352+lane]:0.f, t3b = (lane<4)?sR[484+352+lane]:0.f;
        #pragma unroll
        for (int kk=0;kk<4;kk++){
            a0[kk]=fmaf(t0a,tv[kk].x,a0[kk]); a1[kk]=fmaf(t0b,tv[kk].x,a1[kk]);
            a0[kk]=fmaf(t1a,tv[kk].y,a0[kk]); a1[kk]=fmaf(t1b,tv[kk].y,a1[kk]);
            a0[kk]=fmaf(t2a,tv[kk].z,a0[kk]); a1[kk]=fmaf(t2b,tv[kk].z,a1[kk]);
            a0[kk]=fmaf(t3a,tv[kk].w,a0[kk]); a1[kk]=fmaf(t3b,tv[kk].w,a1[kk]);
        }
        #pragma unroll
        for (int kk=0;kk<4;kk++){
            #pragma unroll
            for (int sh=16; sh; sh>>=1){
                a0[kk] += __shfl_xor_sync(0xffffffffu, a0[kk], sh);
                a1[kk] += __shfl_xor_sync(0xffffffffu, a1[kk], sh);
            }
        }
        if (lane == 0){
            #pragma unroll
            for (int kk=0;kk<4;kk++){
                sLogit[0][w*4+kk] = a0[kk];
                sLogit[1][w*4+kk] = a1[kk];
            }
        }
    }
    __syncthreads();

    if (tid < 2){
        const int h=tid;
        const float ch = g_c[n*2+h];
        float v[KN], m = -3.4e38f;
        #pragma unroll
        for (int k=0;k<KN;k++){
            float x = sLogit[h][k] + ch;
            x = x>=0.f ? x : 0.2f*x;
            v[k]=x; m=fmaxf(m,x);
        }
        float s=0.f;
        #pragma unroll
        for (int k=0;k<KN;k++){ float e=expf(v[k]-m); sAttn[h][k]=e; s+=e; }
        float inv=1.f/s;
        #pragma unroll
        for (int k=0;k<KN;k++) sAttn[h][k]*=inv;
    }
    __syncthreads();

    {
        float at0[4], at1[4];
        #pragma unroll
        for (int kk=0;kk<4;kk++){ at0[kk]=sAttn[0][w*4+kk]; at1[kk]=sAttn[1][w*4+kk]; }
        float4 z0, z1;
        z0=make_float4(0,0,0,0); z1=z0;
        #pragma unroll
        for (int kk=0;kk<4;kk++){
            z0.x=fmaf(at0[kk],sv[kk].x,z0.x); z1.x=fmaf(at1[kk],sv[kk].x,z1.x);
            z0.y=fmaf(at0[kk],sv[kk].y,z0.y); z1.y=fmaf(at1[kk],sv[kk].y,z1.y);
            z0.z=fmaf(at0[kk],sv[kk].z,z0.z); z1.z=fmaf(at1[kk],sv[kk].z,z1.z);
            z0.w=fmaf(at0[kk],sv[kk].w,z0.w); z1.w=fmaf(at1[kk],sv[kk].w,z1.w);
        }
        *(float4*)&sP[w][lane*8  ] = make_float4(z0.x,z1.x,z0.y,z1.y);
        *(float4*)&sP[w][lane*8+4] = make_float4(z0.z,z1.z,z0.w,z1.w);
        z0=make_float4(0,0,0,0); z1=z0;
        #pragma unroll
        for (int kk=0;kk<4;kk++){
            z0.x=fmaf(at0[kk],ev[kk].x,z0.x); z1.x=fmaf(at1[kk],ev[kk].x,z1.x);
            z0.y=fmaf(at0[kk],ev[kk].y,z0.y); z1.y=fmaf(at1[kk],ev[kk].y,z1.y);
            z0.z=fmaf(at0[kk],ev[kk].z,z0.z); z1.z=fmaf(at1[kk],ev[kk].z,z1.z);
            z0.w=fmaf(at0[kk],ev[kk].w,z0.w); z1.w=fmaf(at1[kk],ev[kk].w,z1.w);
        }
        *(float4*)&sP[w][256+lane*8  ] = make_float4(z0.x,z1.x,z0.y,z1.y);
        *(float4*)&sP[w][256+lane*8+4] = make_float4(z0.z,z1.z,z0.w,z1.w);
        z0=make_float4(0,0,0,0); z1=z0;
        #pragma unroll
        for (int kk=0;kk<4;kk++){
            z0.x=fmaf(at0[kk],mv[kk].x,z0.x); z1.x=fmaf(at1[kk],mv[kk].x,z1.x);
            z0.y=fmaf(at0[kk],mv[kk].y,z0.y); z1.y=fmaf(at1[kk],mv[kk].y,z1.y);
            z0.z=fmaf(at0[kk],mv[kk].z,z0.z); z1.z=fmaf(at1[kk],mv[kk].z,z1.z);
            z0.w=fmaf(at0[kk],mv[kk].w,z0.w); z1.w=fmaf(at1[kk],mv[kk].w,z1.w);
        }
        *(float4*)&sP[w][712+lane*8  ] = make_float4(z0.x,z1.x,z0.y,z1.y);
        *(float4*)&sP[w][712+lane*8+4] = make_float4(z0.z,z1.z,z0.w,z1.w);
        float p0,p1;
        p0=0.f; p1=0.f;
        #pragma unroll
        for (int kk=0;kk<4;kk++){ p0=fmaf(at0[kk],tv[kk].x,p0); p1=fmaf(at1[kk],tv[kk].x,p1); }
        *(float2*)&sP[w][512+2*lane] = make_float2(p0,p1);
        p0=0.f; p1=0.f;
        #pragma unroll
        for (int kk=0;kk<4;kk++){ p0=fmaf(at0[kk],tv[kk].y,p0); p1=fmaf(at1[kk],tv[kk].y,p1); }
        *(float2*)&sP[w][576+2*lane] = make_float2(p0,p1);
        p0=0.f; p1=0.f;
        #pragma unroll
        for (int kk=0;kk<4;kk++){ p0=fmaf(at0[kk],tv[kk].z,p0); p1=fmaf(at1[kk],tv[kk].z,p1); }
        *(float2*)&sP[w][640+2*lane] = make_float2(p0,p1);
        if (lane < 4){
            p0=0.f; p1=0.f;
            #pragma unroll
            for (int kk=0;kk<4;kk++){ p0=fmaf(at0[kk],tv[kk].w,p0); p1=fmaf(at1[kk],tv[kk].w,p1); }
            *(float2*)&sP[w][704+2*lane] = make_float2(p0,p1);
        }
    }
    __syncthreads();

    for (int e=tid; e<968; e+=128){
        float s = sP[0][e] + sP[1][e] + sP[2][e] + sP[3][e];
        g_zbar[(size_t)n*968 + e] = s;
    }
}

// ---- K3: attn-out + out-proj + ReLU + LayerNorm (sV overlays sZ) ----
__global__ void __launch_bounds__(128) k3_out(
    const float* __restrict__ b_out, const float* __restrict__ ln_g,
    const float* __restrict__ ln_b,  float* __restrict__ out)
{
    __shared__ float2 sXd[TB][256];
    __shared__ __align__(16) char sOvl[TB*128*4];   // max(sZ 5632B, sV 8192B)
    float4 (*sZ)[22] = reinterpret_cast<float4(*)[22]>(sOvl);
    float  (*sV)[128] = reinterpret_cast<float(*)[128]>(sOvl);
    const int tid=threadIdx.x, row0=blockIdx.x*TB;
    const int d = tid & 31, rg = tid >> 5;

    for (int e=tid; e<TB*128; e+=128){
        float v = g_df[(size_t)row0*128 + e];
        sXd[e>>7][128+(e&127)] = make_float2(v, v);
    }

    u64 acc[4][2];
    #pragma unroll
    for (int r=0;r<4;r++){ acc[r][0]=0ull; acc[r][1]=0ull; }
    const float4* gz4 = (const float4*)g_zbar;
    for (int c=0; c<11; c++){
        __syncthreads();
        for (int e=tid; e<TB*22; e+=128){
            int r=e/22, q=e-r*22;
            sZ[r][q] = __ldg(&gz4[(size_t)(row0+r)*242 + c*22 + q]);
        }
        __syncthreads();
        #pragma unroll 2
        for (int q=0; q<22; q++){
            int jp2 = c*22 + q;
            ulonglong2 wA = *(const ulonglong2*)&g_Wv2[(jp2*64+d)*4];
            ulonglong2 wB = *(const ulonglong2*)&g_Wv2[(jp2*64+d+32)*4];
            #pragma unroll
            for (int r=0;r<4;r++){
                ulonglong2 x = *(const ulonglong2*)&sZ[rg*4+r][q];
                fma2(acc[r][0], wA.x, x.x); fma2(acc[r][0], wA.y, x.y);
                fma2(acc[r][1], wB.x, x.x); fma2(acc[r][1], wB.y, x.y);
            }
        }
    }
    {
        float bA0 = g_bv[d],    bA1 = g_bv[64+d];
        float bB0 = g_bv[d+32], bB1 = g_bv[96+d];
        #pragma unroll
        for (int r=0;r<4;r++){
            int row = rg*4+r;
            float2 a = upk(acc[r][0]);
            float2 b = upk(acc[r][1]);
            float a0 = a.x + bA0, a1 = a.y + bA1;
            float b0 = b.x + bB0, b1 = b.y + bB1;
            sXd[row][d]    = make_float2(a0, a0);
            sXd[row][64+d] = make_float2(a1, a1);
            sXd[row][d+32] = make_float2(b0, b0);
            sXd[row][96+d] = make_float2(b1, b1);
        }
    }
    __syncthreads();
    {
        u64 acc2[4][2];
        #pragma unroll
        for (int r=0;r<4;r++){ acc2[r][0]=0ull; acc2[r][1]=0ull; }
        #pragma unroll 4
        for (int j2=0;j2<128;j2++){
            ulonglong2 wA = *(const ulonglong2*)&g_Wo2[(j2*64+d)*4];
            ulonglong2 wB = *(const ulonglong2*)&g_Wo2[(j2*64+d+32)*4];
            #pragma unroll
            for (int r=0;r<4;r++){
                ulonglong2 x = *(const ulonglong2*)&sXd[rg*4+r][2*j2];
                fma2(acc2[r][0], wA.x, x.x); fma2(acc2[r][0], wA.y, x.y);
                fma2(acc2[r][1], wB.x, x.x); fma2(acc2[r][1], wB.y, x.y);
            }
        }
        float bA0 = b_out[d],    bA1 = b_out[d+64];
        float bB0 = b_out[d+32], bB1 = b_out[d+96];
        #pragma unroll
        for (int r=0;r<4;r++){
            int row = rg*4+r;
            float2 a = upk(acc2[r][0]);
            float2 b = upk(acc2[r][1]);
            sV[row][d]    = fmaxf(a.x + bA0, 0.f);
            sV[row][d+64] = fmaxf(a.y + bA1, 0.f);
            sV[row][d+32] = fmaxf(b.x + bB0, 0.f);
            sV[row][d+96] = fmaxf(b.y + bB1, 0.f);
        }
    }
    __syncthreads();
    const int lane=tid&31, w=tid>>5;
    for (int r=w; r<TB; r+=4){
        float4 x = *(const float4*)&sV[r][lane*4];
        float s = x.x+x.y+x.z+x.w;
        #pragma unroll
        for (int sh=16; sh; sh>>=1) s += __shfl_xor_sync(0xffffffffu, s, sh);
        float mu = s*(1.f/128.f);
        float dx=x.x-mu, dy=x.y-mu, dz=x.z-mu, dw=x.w-mu;
        float q = dx*dx+dy*dy+dz*dz+dw*dw;
        #pragma unroll
        for (int sh=16; sh; sh>>=1) q += __shfl_xor_sync(0xffffffffu, q, sh);
        float rs = rsqrtf(q*(1.f/128.f) + 1e-5f);
        float4 g = *(const float4*)&ln_g[lane*4];
        float4 b = *(const float4*)&ln_b[lane*4];
        float4 y;
        y.x = dx*rs*g.x + b.x; y.y = dy*rs*g.y + b.y;
        y.z = dz*rs*g.z + b.z; y.w = dw*rs*g.w + b.w;
        *(float4*)&out[(size_t)(row0+r)*128 + lane*4] = y;
    }
}

extern "C" void kernel_launch(void* const* d_in, const int* in_sizes, int n_in,
                              void* d_out, int out_size)
{
    const float* memory    = (const float*)d_in[0];
    const float* dst_feat  = (const float*)d_in[1];
    const float* src_feat  = (const float*)d_in[2];
    const float* edge_feat = (const float*)d_in[3];
    const float* dst_ts    = (const float*)d_in[4];
    const float* src_ts    = (const float*)d_in[5];
    const int*   dst_nodes = (const int*)d_in[6];
    const int*   src_nodes = (const int*)d_in[7];
    const float* W_mem     = (const float*)d_in[8];
    const float* b_mem     = (const float*)d_in[9];
    const float* time_w    = (const float*)d_in[10];
    const float* time_b    = (const float*)d_in[11];
    const float* W_q       = (const float*)d_in[12];
    const float* b_q       = (const float*)d_in[13];
    const float* W_kv      = (const float*)d_in[14];
    const float* b_kv      = (const float*)d_in[15];
    const float* W_out     = (const float*)d_in[16];
    const float* b_out     = (const float*)d_in[17];
    const float* ln_g      = (const float*)d_in[18];
    const float* ln_b      = (const float*)d_in[19];
    float* out = (float*)d_out;

    k0_prep<<<256, 128>>>(W_mem, b_mem, W_q, W_kv, b_kv, W_out);
    k1_qdf<<<NB, 128>>>(memory, dst_feat, dst_ts, dst_nodes, b_mem, time_w, time_b, b_q);
    k2_attn<<<NL, 128>>>(memory, src_feat, edge_feat, dst_ts, src_ts, src_nodes, time_w, time_b);
    k3_out<<<NB, 128>>>(b_out, ln_g, ln_b, out);
}

// round 14
// speedup vs baseline: 1.0124x; 1.0124x over previous
#include <cuda_runtime.h>
#include <math.h>

#define NL 50000
#define KN 16
#define TB 16
#define NB (NL/TB)

typedef unsigned long long u64;

// ---------------- persistent device scratch ----------------
__device__ float g_Wm2[64*64*4];
__device__ float g_Wq2[114*64*4];
__device__ float g_Wo2[128*64*4];
__device__ float g_We2[32*512*4];    // jp padded to 512, pad=0
__device__ float g_Wv2[242*64*4];
__device__ float2 g_bk2[64];
__device__ float g_bv[128];
__device__ float g_df  [(size_t)NL*128];
__device__ float g_c   [NL*2];
__device__ float g_rext[(size_t)NL*968];
__device__ float g_zbar[(size_t)NL*968];

__device__ __forceinline__ void fma2(u64 &d, u64 a, u64 b){
    asm("fma.rn.f32x2 %0, %1, %2, %0;" : "+l"(d) : "l"(a), "l"(b));
}
__device__ __forceinline__ float2 upk(u64 v){
    float lo, hi;
    asm("mov.b64 {%0,%1}, %2;" : "=f"(lo), "=f"(hi) : "l"(v));
    return make_float2(lo, hi);
}
__device__ __forceinline__ float dot4(float4 a, float4 b){
    return fmaf(a.x,b.x, fmaf(a.y,b.y, fmaf(a.z,b.z, a.w*b.w)));
}

// ---- K0: build packed weights ----
__global__ void k0_prep(const float* __restrict__ W_mem, const float* __restrict__ b_mem,
                        const float* __restrict__ W_q,   const float* __restrict__ W_kv,
                        const float* __restrict__ b_kv,  const float* __restrict__ W_out)
{
    const int t = blockIdx.x*blockDim.x + threadIdx.x, nt = gridDim.x*blockDim.x;
    for (int e=t; e<64*64*4; e+=nt){
        int s=e&3, po=(e>>2)&63, j2=e>>8;
        g_Wm2[e] = W_mem[(po + 64*(s&1))*128 + 2*j2 + (s>>1)];
    }
    for (int e=t; e<114*64*4; e+=nt){
        int s=e&3, po=(e>>2)&63, j2=e>>8;
        g_Wq2[e] = W_q[(po + 64*(s&1))*228 + 2*j2 + (s>>1)];
    }
    for (int e=t; e<128*64*4; e+=nt){
        int s=e&3, po=(e>>2)&63, j2=e>>8;
        g_Wo2[e] = W_out[(po + 64*(s&1))*256 + 2*j2 + (s>>1)];
    }
    for (int e=t; e<32*512*4; e+=nt){
        int s=e&3, r=e>>2, jp=r&511, d2=r>>9;
        int d = 2*d2 + (s>>1), h = s&1, i = h*64 + d;
        float v = 0.f;
        if (jp < 484){
            if (jp < 356) v = W_kv[i*356 + jp];
            else { int m=jp-356; float acc=0.f;
                   for (int l=0;l<128;l++) acc = fmaf(W_kv[i*356+l], W_mem[l*128+m], acc);
                   v = acc; }
        }
        g_We2[e] = v;
    }
    for (int e=t; e<242*64*4; e+=nt){
        int s=e&3, r=e>>2, d=r&63, jp2=r>>6;
        int jp = 2*jp2 + (s>>1), h = s&1, i = 128 + h*64 + d;
        float v;
        if (jp < 356) v = W_kv[i*356 + jp];
        else { int m=jp-356; float acc=0.f;
               for (int l=0;l<128;l++) acc = fmaf(W_kv[i*356+l], W_mem[l*128+m], acc);
               v = acc; }
        g_Wv2[e] = v;
    }
    for (int e=t; e<256; e+=nt){
        float s = b_kv[e];
        for (int l=0;l<128;l++) s = fmaf(W_kv[e*356+l], b_mem[l], s);
        if (e < 128){
            if (e < 64) g_bk2[e].x = s; else g_bk2[e-64].y = s;
        } else g_bv[e-128] = s;
    }
}

// ---- K1: df, t_dst, Q, c, rext ----
__global__ void __launch_bounds__(128) k1_qdf(
    const float* __restrict__ memory, const float* __restrict__ dst_feat,
    const float* __restrict__ dst_ts, const int* __restrict__ dst_nodes,
    const float* __restrict__ b_mem,  const float* __restrict__ time_w,
    const float* __restrict__ time_b, const float* __restrict__ b_q)
{
    __shared__ float2 sXd[TB][228];
    __shared__ float2 sMQ[TB][128];
    __shared__ int   sIdx[TB];
    __shared__ float sTs[TB];
    const int tid = threadIdx.x, row0 = blockIdx.x*TB;

    if (tid < TB){ sIdx[tid]=dst_nodes[row0+tid]; sTs[tid]=dst_ts[row0+tid]; }
    __syncthreads();
    for (int e=tid; e<TB*128; e+=128){
        int r=e>>7, c=e&127;
        float v = __ldg(&memory[(size_t)sIdx[r]*128 + c]);
        sMQ[r][c] = make_float2(v, v);
    }
    for (int e=tid; e<TB*100; e+=128){
        int r=e/100, d=e-r*100;
        float v = __cosf(fmaf(sTs[r], time_w[d], time_b[d]));
        sXd[r][128+d] = make_float2(v, v);
    }
    __syncthreads();

    const int po = tid & 63, rg = tid >> 6;
    { // df
        u64 acc[8];
        #pragma unroll
        for (int r=0;r<8;r++) acc[r]=0ull;
        for (int j2=0;j2<64;j2++){
            ulonglong2 w = *(const ulonglong2*)&g_Wm2[(j2*64+po)*4];
            #pragma unroll
            for (int r=0;r<8;r++){
                ulonglong2 x = *(const ulonglong2*)&sMQ[rg*8+r][2*j2];
                fma2(acc[r], w.x, x.x);
                fma2(acc[r], w.y, x.y);
            }
        }
        float bl = b_mem[po], bh = b_mem[po+64];
        #pragma unroll
        for (int r=0;r<8;r++){
            int row = rg*8+r;
            float2 a = upk(acc[r]);
            float lo = a.x + bl + dst_feat[(size_t)(row0+row)*128 + po];
            float hi = a.y + bh + dst_feat[(size_t)(row0+row)*128 + po + 64];
            sXd[row][po]    = make_float2(lo, lo);
            sXd[row][po+64] = make_float2(hi, hi);
            g_df[(size_t)(row0+row)*128 + po]      = lo;
            g_df[(size_t)(row0+row)*128 + po + 64] = hi;
        }
    }
    __syncthreads();
    { // Q
        u64 acc[8];
        #pragma unroll
        for (int r=0;r<8;r++) acc[r]=0ull;
        for (int j2=0;j2<114;j2++){
            ulonglong2 w = *(const ulonglong2*)&g_Wq2[(j2*64+po)*4];
            #pragma unroll
            for (int r=0;r<8;r++){
                ulonglong2 x = *(const ulonglong2*)&sXd[rg*8+r][2*j2];
                fma2(acc[r], w.x, x.x);
                fma2(acc[r], w.y, x.y);
            }
        }
        float bl = b_q[po], bh = b_q[po+64];
        #pragma unroll
        for (int r=0;r<8;r++){
            float2 a = upk(acc[r]);
            sMQ[rg*8+r][po] = make_float2(a.x + bl, a.y + bh);
        }
    }
    __syncthreads();
    if (tid < TB){
        float c0=0.f, c1=0.f;
        for (int d=0;d<64;d++){
            float2 q = sMQ[tid][d], b = g_bk2[d];
            c0 = fmaf(q.x, b.x, c0); c1 = fmaf(q.y, b.y, c1);
        }
        g_c[(row0+tid)*2+0]=c0; g_c[(row0+tid)*2+1]=c1;
    }
    #pragma unroll
    for (int half=0; half<2; half++){
        #pragma unroll
        for (int it=0; it<2; it++){
            const int jpA = tid + it*128;
            const int jpB = jpA + 256;
            u64 aA[8], aB[8];
            #pragma unroll
            for (int r=0;r<8;r++){ aA[r]=0ull; aB[r]=0ull; }
            for (int d2=0;d2<32;d2++){
                ulonglong2 wA = *(const ulonglong2*)&g_We2[(d2*512+jpA)*4];
                ulonglong2 wB = *(const ulonglong2*)&g_We2[(d2*512+jpB)*4];
                #pragma unroll
                for (int r=0;r<8;r++){
                    ulonglong2 x = *(const ulonglong2*)&sMQ[half*8+r][2*d2];
                    fma2(aA[r], wA.x, x.x); fma2(aA[r], wA.y, x.y);
                    fma2(aB[r], wB.x, x.x); fma2(aB[r], wB.y, x.y);
                }
            }
            #pragma unroll
            for (int r=0;r<8;r++){
                int row = row0 + half*8 + r;
                *(float2*)&g_rext[(size_t)row*968 + jpA*2] = upk(aA[r]);
                if (jpB < 484)
                    *(float2*)&g_rext[(size_t)row*968 + jpB*2] = upk(aB[r]);
            }
        }
    }
}

// ---- K2: register-resident features; tv recomputed in phase D (reg cap 6 blocks) ----
__global__ void __launch_bounds__(128, 6) k2_attn(
    const float* __restrict__ memory,  const float* __restrict__ src_feat,
    const float* __restrict__ edge_feat, const float* __restrict__ dst_ts,
    const float* __restrict__ src_ts,  const int* __restrict__ src_nodes,
    const float* __restrict__ time_w,  const float* __restrict__ time_b)
{
    __shared__ float sR[968];
    __shared__ float sP[4][968];
    __shared__ float sLogit[2][KN];
    __shared__ float sAttn[2][KN];
    const int n=blockIdx.x, tid=threadIdx.x, lane=tid&31, w=tid>>5;

    for (int e=tid; e<968; e+=128){
        float v = g_rext[(size_t)n*968 + e];
        sR[(e&1)*484 + (e>>1)] = v;
    }

    float4 sv[4], ev[4], mv[4];
    float dt[4];
    const float dts = dst_ts[n];
    #pragma unroll
    for (int kk=0; kk<4; kk++){
        const int k = w*4 + kk;
        const size_t eb = ((size_t)n*KN + k)*128;
        const int idx = src_nodes[n*KN + k];
        sv[kk] = *(const float4*)&src_feat [eb + lane*4];
        ev[kk] = *(const float4*)&edge_feat[eb + lane*4];
        mv[kk] = __ldg((const float4*)&memory[(size_t)idx*128 + lane*4]);
        float d = dts - src_ts[n*KN + k];
        dt[kk] = d > 0.f ? d : 0.f;
    }
    __syncthreads();

    { // Phase B: logits (tv computed on the fly)
        const float tw0=__ldg(&time_w[lane]),    tb0=__ldg(&time_b[lane]);
        const float tw1=__ldg(&time_w[lane+32]), tb1=__ldg(&time_b[lane+32]);
        const float tw2=__ldg(&time_w[lane+64]), tb2=__ldg(&time_b[lane+64]);
        const float tw3=(lane<4)?__ldg(&time_w[lane+96]):0.f;
        const float tb3=(lane<4)?__ldg(&time_b[lane+96]):0.f;
        float a0[4], a1[4];
        #pragma unroll
        for (int kk=0;kk<4;kk++){ a0[kk]=0.f; a1[kk]=0.f; }
        float4 r0, r1;
        r0 = *(const float4*)&sR[lane*4];       r1 = *(const float4*)&sR[484+lane*4];
        #pragma unroll
        for (int kk=0;kk<4;kk++){ a0[kk]+=dot4(r0,sv[kk]); a1[kk]+=dot4(r1,sv[kk]); }
        r0 = *(const float4*)&sR[128+lane*4];   r1 = *(const float4*)&sR[484+128+lane*4];
        #pragma unroll
        for (int kk=0;kk<4;kk++){ a0[kk]+=dot4(r0,ev[kk]); a1[kk]+=dot4(r1,ev[kk]); }
        r0 = *(const float4*)&sR[356+lane*4];   r1 = *(const float4*)&sR[484+356+lane*4];
        #pragma unroll
        for (int kk=0;kk<4;kk++){ a0[kk]+=dot4(r0,mv[kk]); a1[kk]+=dot4(r1,mv[kk]); }
        float t0a = sR[256+lane], t0b = sR[484+256+lane];
        float t1a = sR[288+lane], t1b = sR[484+288+lane];
        float t2a = sR[320+lane], t2b = sR[484+320+lane];
        float t3a = (lane<4)?sR[352+lane]:0.f, t3b = (lane<4)?sR[484+352+lane]:0.f;
        #pragma unroll
        for (int kk=0;kk<4;kk++){
            float v0 = __cosf(fmaf(dt[kk], tw0, tb0));
            float v1 = __cosf(fmaf(dt[kk], tw1, tb1));
            float v2 = __cosf(fmaf(dt[kk], tw2, tb2));
            float v3 = (lane<4) ? __cosf(fmaf(dt[kk], tw3, tb3)) : 0.f;
            a0[kk]=fmaf(t0a,v0,a0[kk]); a1[kk]=fmaf(t0b,v0,a1[kk]);
            a0[kk]=fmaf(t1a,v1,a0[kk]); a1[kk]=fmaf(t1b,v1,a1[kk]);
            a0[kk]=fmaf(t2a,v2,a0[kk]); a1[kk]=fmaf(t2b,v2,a1[kk]);
            a0[kk]=fmaf(t3a,v3,a0[kk]); a1[kk]=fmaf(t3b,v3,a1[kk]);
        }
        #pragma unroll
        for (int kk=0;kk<4;kk++){
            #pragma unroll
            for (int sh=16; sh; sh>>=1){
                a0[kk] += __shfl_xor_sync(0xffffffffu, a0[kk], sh);
                a1[kk] += __shfl_xor_sync(0xffffffffu, a1[kk], sh);
            }
        }
        if (lane == 0){
            #pragma unroll
            for (int kk=0;kk<4;kk++){
                sLogit[0][w*4+kk] = a0[kk];
                sLogit[1][w*4+kk] = a1[kk];
            }
        }
    }
    __syncthreads();

    if (tid < 2){
        const int h=tid;
        const float ch = g_c[n*2+h];
        float v[KN], m = -3.4e38f;
        #pragma unroll
        for (int k=0;k<KN;k++){
            float x = sLogit[h][k] + ch;
            x = x>=0.f ? x : 0.2f*x;
            v[k]=x; m=fmaxf(m,x);
        }
        float s=0.f;
        #pragma unroll
        for (int k=0;k<KN;k++){ float e=expf(v[k]-m); sAttn[h][k]=e; s+=e; }
        float inv=1.f/s;
        #pragma unroll
        for (int k=0;k<KN;k++) sAttn[h][k]*=inv;
    }
    __syncthreads();

    { // Phase D: partial zbar; tv recomputed via MUFU
        float at0[4], at1[4];
        #pragma unroll
        for (int kk=0;kk<4;kk++){ at0[kk]=sAttn[0][w*4+kk]; at1[kk]=sAttn[1][w*4+kk]; }
        float4 z0, z1;
        z0=make_float4(0,0,0,0); z1=z0;
        #pragma unroll
        for (int kk=0;kk<4;kk++){
            z0.x=fmaf(at0[kk],sv[kk].x,z0.x); z1.x=fmaf(at1[kk],sv[kk].x,z1.x);
            z0.y=fmaf(at0[kk],sv[kk].y,z0.y); z1.y=fmaf(at1[kk],sv[kk].y,z1.y);
            z0.z=fmaf(at0[kk],sv[kk].z,z0.z); z1.z=fmaf(at1[kk],sv[kk].z,z1.z);
            z0.w=fmaf(at0[kk],sv[kk].w,z0.w); z1.w=fmaf(at1[kk],sv[kk].w,z1.w);
        }
        *(float4*)&sP[w][lane*8  ] = make_float4(z0.x,z1.x,z0.y,z1.y);
        *(float4*)&sP[w][lane*8+4] = make_float4(z0.z,z1.z,z0.w,z1.w);
        z0=make_float4(0,0,0,0); z1=z0;
        #pragma unroll
        for (int kk=0;kk<4;kk++){
            z0.x=fmaf(at0[kk],ev[kk].x,z0.x); z1.x=fmaf(at1[kk],ev[kk].x,z1.x);
            z0.y=fmaf(at0[kk],ev[kk].y,z0.y); z1.y=fmaf(at1[kk],ev[kk].y,z1.y);
            z0.z=fmaf(at0[kk],ev[kk].z,z0.z); z1.z=fmaf(at1[kk],ev[kk].z,z1.z);
            z0.w=fmaf(at0[kk],ev[kk].w,z0.w); z1.w=fmaf(at1[kk],ev[kk].w,z1.w);
        }
        *(float4*)&sP[w][256+lane*8  ] = make_float4(z0.x,z1.x,z0.y,z1.y);
        *(float4*)&sP[w][256+lane*8+4] = make_float4(z0.z,z1.z,z0.w,z1.w);
        z0=make_float4(0,0,0,0); z1=z0;
        #pragma unroll
        for (int kk=0;kk<4;kk++){
            z0.x=fmaf(at0[kk],mv[kk].x,z0.x); z1.x=fmaf(at1[kk],mv[kk].x,z1.x);
            z0.y=fmaf(at0[kk],mv[kk].y,z0.y); z1.y=fmaf(at1[kk],mv[kk].y,z1.y);
            z0.z=fmaf(at0[kk],mv[kk].z,z0.z); z1.z=fmaf(at1[kk],mv[kk].z,z1.z);
            z0.w=fmaf(at0[kk],mv[kk].w,z0.w); z1.w=fmaf(at1[kk],mv[kk].w,z1.w);
        }
        *(float4*)&sP[w][712+lane*8  ] = make_float4(z0.x,z1.x,z0.y,z1.y);
        *(float4*)&sP[w][712+lane*8+4] = make_float4(z0.z,z1.z,z0.w,z1.w);
        const float tw0=__ldg(&time_w[lane]),    tb0=__ldg(&time_b[lane]);
        const float tw1=__ldg(&time_w[lane+32]), tb1=__ldg(&time_b[lane+32]);
        const float tw2=__ldg(&time_w[lane+64]), tb2=__ldg(&time_b[lane+64]);
        float p0,p1;
        p0=0.f; p1=0.f;
        #pragma unroll
        for (int kk=0;kk<4;kk++){ float v=__cosf(fmaf(dt[kk],tw0,tb0));
            p0=fmaf(at0[kk],v,p0); p1=fmaf(at1[kk],v,p1); }
        *(float2*)&sP[w][512+2*lane] = make_float2(p0,p1);
        p0=0.f; p1=0.f;
        #pragma unroll
        for (int kk=0;kk<4;kk++){ float v=__cosf(fmaf(dt[kk],tw1,tb1));
            p0=fmaf(at0[kk],v,p0); p1=fmaf(at1[kk],v,p1); }
        *(float2*)&sP[w][576+2*lane] = make_float2(p0,p1);
        p0=0.f; p1=0.f;
        #pragma unroll
        for (int kk=0;kk<4;kk++){ float v=__cosf(fmaf(dt[kk],tw2,tb2));
            p0=fmaf(at0[kk],v,p0); p1=fmaf(at1[kk],v,p1); }
        *(float2*)&sP[w][640+2*lane] = make_float2(p0,p1);
        if (lane < 4){
            const float tw3=__ldg(&time_w[lane+96]), tb3=__ldg(&time_b[lane+96]);
            p0=0.f; p1=0.f;
            #pragma unroll
            for (int kk=0;kk<4;kk++){ float v=__cosf(fmaf(dt[kk],tw3,tb3));
                p0=fmaf(at0[kk],v,p0); p1=fmaf(at1[kk],v,p1); }
            *(float2*)&sP[w][704+2*lane] = make_float2(p0,p1);
        }
    }
    __syncthreads();

    for (int e=tid; e<968; e+=128){
        float s = sP[0][e] + sP[1][e] + sP[2][e] + sP[3][e];
        g_zbar[(size_t)n*968 + e] = s;
    }
}

// ---- K3: attn-out + out-proj + ReLU + LayerNorm (sV overlays sZ) ----
__global__ void __launch_bounds__(128) k3_out(
    const float* __restrict__ b_out, const float* __restrict__ ln_g,
    const float* __restrict__ ln_b,  float* __restrict__ out)
{
    __shared__ float2 sXd[TB][256];
    __shared__ __align__(16) char sOvl[TB*128*4];
    float4 (*sZ)[22] = reinterpret_cast<float4(*)[22]>(sOvl);
    float  (*sV)[128] = reinterpret_cast<float(*)[128]>(sOvl);
    const int tid=threadIdx.x, row0=blockIdx.x*TB;
    const int d = tid & 31, rg = tid >> 5;

    for (int e=tid; e<TB*128; e+=128){
        float v = g_df[(size_t)row0*128 + e];
        sXd[e>>7][128+(e&127)] = make_float2(v, v);
    }

    u64 acc[4][2];
    #pragma unroll
    for (int r=0;r<4;r++){ acc[r][0]=0ull; acc[r][1]=0ull; }
    const float4* gz4 = (const float4*)g_zbar;
    for (int c=0; c<11; c++){
        __syncthreads();
        for (int e=tid; e<TB*22; e+=128){
            int r=e/22, q=e-r*22;
            sZ[r][q] = __ldg(&gz4[(size_t)(row0+r)*242 + c*22 + q]);
        }
        __syncthreads();
        #pragma unroll 2
        for (int q=0; q<22; q++){
            int jp2 = c*22 + q;
            ulonglong2 wA = *(const ulonglong2*)&g_Wv2[(jp2*64+d)*4];
            ulonglong2 wB = *(const ulonglong2*)&g_Wv2[(jp2*64+d+32)*4];
            #pragma unroll
            for (int r=0;r<4;r++){
                ulonglong2 x = *(const ulonglong2*)&sZ[rg*4+r][q];
                fma2(acc[r][0], wA.x, x.x); fma2(acc[r][0], wA.y, x.y);
                fma2(acc[r][1], wB.x, x.x); fma2(acc[r][1], wB.y, x.y);
            }
        }
    }
    {
        float bA0 = g_bv[d],    bA1 = g_bv[64+d];
        float bB0 = g_bv[d+32], bB1 = g_bv[96+d];
        #pragma unroll
        for (int r=0;r<4;r++){
            int row = rg*4+r;
            float2 a = upk(acc[r][0]);
            float2 b = upk(acc[r][1]);
            float a0 = a.x + bA0, a1 = a.y + bA1;
            float b0 = b.x + bB0, b1 = b.y + bB1;
            sXd[row][d]    = make_float2(a0, a0);
            sXd[row][64+d] = make_float2(a1, a1);
            sXd[row][d+32] = make_float2(b0, b0);
            sXd[row][96+d] = make_float2(b1, b1);
        }
    }
    __syncthreads();
    {
        u64 acc2[4][2];
        #pragma unroll
        for (int r=0;r<4;r++){ acc2[r][0]=0ull; acc2[r][1]=0ull; }
        #pragma unroll 4
        for (int j2=0;j2<128;j2++){
            ulonglong2 wA = *(const ulonglong2*)&g_Wo2[(j2*64+d)*4];
            ulonglong2 wB = *(const ulonglong2*)&g_Wo2[(j2*64+d+32)*4];
            #pragma unroll
            for (int r=0;r<4;r++){
                ulonglong2 x = *(const ulonglong2*)&sXd[rg*4+r][2*j2];
                fma2(acc2[r][0], wA.x, x.x); fma2(acc2[r][0], wA.y, x.y);
                fma2(acc2[r][1], wB.x, x.x); fma2(acc2[r][1], wB.y, x.y);
            }
        }
        float bA0 = b_out[d],    bA1 = b_out[d+64];
        float bB0 = b_out[d+32], bB1 = b_out[d+96];
        #pragma unroll
        for (int r=0;r<4;r++){
            int row = rg*4+r;
            float2 a = upk(acc2[r][0]);
            float2 b = upk(acc2[r][1]);
            sV[row][d]    = fmaxf(a.x + bA0, 0.f);
            sV[row][d+64] = fmaxf(a.y + bA1, 0.f);
            sV[row][d+32] = fmaxf(b.x + bB0, 0.f);
            sV[row][d+96] = fmaxf(b.y + bB1, 0.f);
        }
    }
    __syncthreads();
    const int lane=tid&31, w=tid>>5;
    for (int r=w; r<TB; r+=4){
        float4 x = *(const float4*)&sV[r][lane*4];
        float s = x.x+x.y+x.z+x.w;
        #pragma unroll
        for (int sh=16; sh; sh>>=1) s += __shfl_xor_sync(0xffffffffu, s, sh);
        float mu = s*(1.f/128.f);
        float dx=x.x-mu, dy=x.y-mu, dz=x.z-mu, dw=x.w-mu;
        float q = dx*dx+dy*dy+dz*dz+dw*dw;
        #pragma unroll
        for (int sh=16; sh; sh>>=1) q += __shfl_xor_sync(0xffffffffu, q, sh);
        float rs = rsqrtf(q*(1.f/128.f) + 1e-5f);
        float4 g = *(const float4*)&ln_g[lane*4];
        float4 b = *(const float4*)&ln_b[lane*4];
        float4 y;
        y.x = dx*rs*g.x + b.x; y.y = dy*rs*g.y + b.y;
        y.z = dz*rs*g.z + b.z; y.w = dw*rs*g.w + b.w;
        *(float4*)&out[(size_t)(row0+r)*128 + lane*4] = y;
    }
}

extern "C" void kernel_launch(void* const* d_in, const int* in_sizes, int n_in,
                              void* d_out, int out_size)
{
    const float* memory    = (const float*)d_in[0];
    const float* dst_feat  = (const float*)d_in[1];
    const float* src_feat  = (const float*)d_in[2];
    const float* edge_feat = (const float*)d_in[3];
    const float* dst_ts    = (const float*)d_in[4];
    const float* src_ts    = (const float*)d_in[5];
    const int*   dst_nodes = (const int*)d_in[6];
    const int*   src_nodes = (const int*)d_in[7];
    const float* W_mem     = (const float*)d_in[8];
    const float* b_mem     = (const float*)d_in[9];
    const float* time_w    = (const float*)d_in[10];
    const float* time_b    = (const float*)d_in[11];
    const float* W_q       = (const float*)d_in[12];
    const float* b_q       = (const float*)d_in[13];
    const float* W_kv      = (const float*)d_in[14];
    const float* b_kv      = (const float*)d_in[15];
    const float* W_out     = (const float*)d_in[16];
    const float* b_out     = (const float*)d_in[17];
    const float* ln_g      = (const float*)d_in[18];
    const float* ln_b      = (const float*)d_in[19];
    float* out = (float*)d_out;

    k0_prep<<<256, 128>>>(W_mem, b_mem, W_q, W_kv, b_kv, W_out);
    k1_qdf<<<NB, 128>>>(memory, dst_feat, dst_ts, dst_nodes, b_mem, time_w, time_b, b_q);
    k2_attn<<<NL, 128>>>(memory, src_feat, edge_feat, dst_ts, src_ts, src_nodes, time_w, time_b);
    k3_out<<<NB, 128>>>(b_out, ln_g, ln_b, out);
}